// round 15
// baseline (speedup 1.0000x reference)
#include <cuda_runtime.h>
#include <cuda_bf16.h>
#include <cstdint>

#define B_    128
#define S_    512
#define D_    2048
#define N_    128
#define NN_   16384
#define KTILE 64
#define ABW   144    /* A (bf16) smem row stride bytes: 128 data + 16 pad */
#define BPAD  72     /* B (fp32) smem row stride floats: 64 data + 8 pad */
#define BRS   (BPAD * 4)
#define STG   4
#define ATB   (128 * ABW)

// ---------------- scratch (device globals; no allocation) ----------------
__device__ __align__(16) __nv_bfloat16 g_meanbf[B_ * D_];  // 0.5 MB
__device__ __align__(16) __nv_bfloat16 g_ctxbf[B_ * D_];   // 0.5 MB (bf16 ctx, gemm2 A)
__device__ __align__(16) float g_ctxp[2 * B_ * D_];        // 2 MB gemm1 split-K partials
__device__ __align__(16) float g_part[128 * NN_];          // 8 MB raw split-K partials
__device__ __align__(16) float g_raw [NN_];                // 64 KB

// ---------------- helpers ----------------
__device__ __forceinline__ uint32_t f2bf2(float lo, float hi) {
    uint32_t r;
    asm("cvt.rn.bf16x2.f32 %0, %1, %2;" : "=r"(r) : "f"(hi), "f"(lo));  // hi -> upper 16
    return r;
}
__device__ __forceinline__ void mma_bf16(float* c, const uint32_t* a, const uint32_t* b) {
    asm volatile(
        "mma.sync.aligned.m16n8k16.row.col.f32.bf16.bf16.f32 "
        "{%0,%1,%2,%3}, {%4,%5,%6,%7}, {%8,%9}, {%0,%1,%2,%3};"
        : "+f"(c[0]), "+f"(c[1]), "+f"(c[2]), "+f"(c[3])
        : "r"(a[0]), "r"(a[1]), "r"(a[2]), "r"(a[3]), "r"(b[0]), "r"(b[1]));
}
__device__ __forceinline__ void bulk_g2s(uint32_t dst, const void* src, uint32_t bytes,
                                         uint32_t mbar) {
    asm volatile(
        "cp.async.bulk.shared::cluster.global.mbarrier::complete_tx::bytes "
        "[%0], [%1], %2, [%3];"
        :: "r"(dst), "l"(src), "r"(bytes), "r"(mbar) : "memory");
}
__device__ __forceinline__ void mbar_init(uint32_t a, uint32_t cnt) {
    asm volatile("mbarrier.init.shared.b64 [%0], %1;" :: "r"(a), "r"(cnt) : "memory");
}
__device__ __forceinline__ void mbar_expect(uint32_t a, uint32_t bytes) {
    asm volatile("mbarrier.arrive.expect_tx.shared.b64 _, [%0], %1;"
                 :: "r"(a), "r"(bytes) : "memory");
}
__device__ __forceinline__ void mbar_wait(uint32_t a, uint32_t parity) {
    asm volatile(
        "{\n\t.reg .pred P;\n\t"
        "LW%=:\n\t"
        "mbarrier.try_wait.parity.acquire.cta.shared::cta.b64 P, [%0], %1, 0x989680;\n\t"
        "@P bra.uni LD%=;\n\t"
        "bra.uni LW%=;\n\t"
        "LD%=:\n\t}"
        :: "r"(a), "r"(parity) : "memory");
}

// ---------------- kernel 1: mean over sequence -> bf16 ----------------
__global__ void k_mean(const float4* __restrict__ x4, uint2* __restrict__ mbf) {
    int b  = blockIdx.x >> 3;
    int d4 = ((blockIdx.x & 7) << 6) + threadIdx.x;     // 0..511
    const float4* p = x4 + (size_t)b * (S_ * D_ / 4) + d4;
    float4 acc[8];
    #pragma unroll
    for (int u = 0; u < 8; u++) acc[u] = make_float4(0.f, 0.f, 0.f, 0.f);
    for (int s = 0; s < S_; s += 8) {
        #pragma unroll
        for (int u = 0; u < 8; u++) {
            float4 v = __ldcs(&p[(size_t)(s + u) * (D_ / 4)]);
            acc[u].x += v.x; acc[u].y += v.y; acc[u].z += v.z; acc[u].w += v.w;
        }
    }
    #pragma unroll
    for (int u = 0; u < 4; u++) {
        acc[u].x += acc[u+4].x; acc[u].y += acc[u+4].y;
        acc[u].z += acc[u+4].z; acc[u].w += acc[u+4].w;
    }
    acc[0].x += acc[2].x; acc[0].y += acc[2].y; acc[0].z += acc[2].z; acc[0].w += acc[2].w;
    acc[1].x += acc[3].x; acc[1].y += acc[3].y; acc[1].z += acc[3].z; acc[1].w += acc[3].w;
    const float inv = 1.f / (float)S_;
    float mx = (acc[0].x + acc[1].x) * inv;
    float my = (acc[0].y + acc[1].y) * inv;
    float mz = (acc[0].z + acc[1].z) * inv;
    float mw = (acc[0].w + acc[1].w) * inv;
    mbf[b * (D_ / 4) + d4] = make_uint2(f2bf2(mx, my), f2bf2(mz, mw));
}

// ---------------- bulk-copy 4-stage GEMM: A bf16-smem, B fp32-smem ----------------
// Tiles land via cp.async.bulk (one row per thread) tracked by per-stage mbarrier.
// 256 threads = 8 warps laid out WY(M) x WX(N). One __syncthreads per ktile.
// MODE 0: split-K x2 partials. grid = 2 * NFULL/NT. out[split][128][NFULL] raw acc.
// MODE 3: full-K + fused softmax/einsum/sigmoid epilogue (NT = 128).
template<int NT, int NFULL, int MODE, int WY, int WX>
__global__ void __launch_bounds__(256, 1)
k_gemm(const __nv_bfloat16* __restrict__ Abf, const float* __restrict__ Bm,
       const float* __restrict__ bias, float* __restrict__ out,
       const float* __restrict__ adj, const float* __restrict__ raw) {
    constexpr int BTB    = NT * BRS;          // B tile bytes per stage
    constexpr int MW     = 128 / WY / 16;     // m16 tiles per warp
    constexpr int NJ     = NT / WX / 8;       // n8 tiles per warp
    constexpr uint32_t XBYTES = 128 * 128 + NT * 256;   // expected tx per stage

    extern __shared__ __align__(16) char smch[];
    float* sm = (float*)smch;
    char* Ab = smch + 64;                     // [STG][128][ABW]
    char* Bb = Ab + STG * ATB;                // [STG][NT][BRS]
    const uint32_t smb  = (uint32_t)__cvta_generic_to_shared(smch);
    const uint32_t abU  = smb + 64;
    const uint32_t bbU  = abU + STG * ATB;

    const int tid  = threadIdx.x;
    const int warp = tid >> 5, lane = tid & 31;
    const int wy   = warp / WX, wx = warp % WX;
    const int row0 = wy * (128 / WY);
    const int wxn0 = wx * (NT / WX);
    const int r    = lane >> 2, c = lane & 3;

    int n0, k0g, nkt;
    float* op = out;
    if (MODE == 0) {
        const int nblk = NFULL / NT;
        int split = blockIdx.x / nblk;
        n0  = (blockIdx.x % nblk) * NT;
        k0g = split * (D_ / 2);
        nkt = (D_ / 2) / KTILE;               // 16
        op  = out + (size_t)split * 128 * NFULL;
    } else {
        n0 = blockIdx.x * NT; k0g = 0; nkt = D_ / KTILE;   // 32
    }

    float acc[MW][NJ][4];
    #pragma unroll
    for (int m = 0; m < MW; m++)
        #pragma unroll
        for (int j = 0; j < NJ; j++)
            acc[m][j][0] = acc[m][j][1] = acc[m][j][2] = acc[m][j][3] = 0.f;

    auto issue = [&](int kt) {
        const int st = kt % STG;
        const int k0 = k0g + kt * KTILE;
        if (tid == 0) mbar_expect(smb + st * 8, XBYTES);
        if (tid < 128) {
            bulk_g2s(abU + st * ATB + tid * ABW,
                     Abf + (size_t)tid * D_ + k0, 128, smb + st * 8);
        } else if (tid - 128 < NT) {
            const int row = tid - 128;
            bulk_g2s(bbU + st * BTB + row * BRS,
                     Bm + (size_t)(n0 + row) * D_ + k0, 256, smb + st * 8);
        }
    };

    if (tid == 0)
        for (int s = 0; s < STG; s++) mbar_init(smb + s * 8, 1);
    __syncthreads();
    #pragma unroll
    for (int s = 0; s < STG - 1; s++) issue(s);

    for (int kt = 0; kt < nkt; kt++) {
        const int st = kt % STG;
        mbar_wait(smb + st * 8, (uint32_t)((kt / STG) & 1));
        __syncthreads();
        // issue(kt+3) overwrites stage (kt-1)%4; consumed at iter kt-1, and all
        // threads passed that compute before this iteration's sync. Safe.
        if (kt + STG - 1 < nkt) issue(kt + STG - 1);

        const char*  Ast = Ab + st * ATB;
        const float* Bst = (const float*)(Bb + st * BTB);
        #pragma unroll
        for (int h = 0; h < 4; h++) {
            const int cb = h * 32 + 4 * c;            // A byte offset of k = 16h + 2c
            const int kb = h * 16 + 2 * c;            // B float offset
            uint32_t a[MW][4];
            #pragma unroll
            for (int m = 0; m < MW; m++) {
                const char* ap = Ast + (row0 + m * 16 + r) * ABW;
                a[m][0] = *(const uint32_t*)(ap + cb);
                a[m][1] = *(const uint32_t*)(ap + 8 * ABW + cb);
                a[m][2] = *(const uint32_t*)(ap + cb + 16);
                a[m][3] = *(const uint32_t*)(ap + 8 * ABW + cb + 16);
            }
            #pragma unroll
            for (int j = 0; j < NJ; j++) {
                const float* bp = Bst + (wxn0 + j * 8 + r) * BPAD + kb;
                float2 v;
                uint32_t b[2];
                v = *(const float2*)(bp);       b[0] = f2bf2(v.x, v.y);
                v = *(const float2*)(bp + 8);   b[1] = f2bf2(v.x, v.y);
                #pragma unroll
                for (int m = 0; m < MW; m++) mma_bf16(acc[m][j], a[m], b);
            }
        }
    }

    if (MODE == 0) {
        #pragma unroll
        for (int m = 0; m < MW; m++)
            #pragma unroll
            for (int j = 0; j < NJ; j++) {
                int row = row0 + m * 16 + r;
                int col = n0 + wxn0 + j * 8 + 2 * c;
                *(float2*)&op[(size_t)row * NFULL + col] =
                    make_float2(acc[m][j][0], acc[m][j][1]);
                *(float2*)&op[(size_t)(row + 8) * NFULL + col] =
                    make_float2(acc[m][j][2], acc[m][j][3]);
            }
    } else {
        // fused: logits = adj[i,:] + 0.1*(acc + bw); softmax over j; dot raw; sigmoid
        __syncthreads();
        float* logit = sm;                 // [128][130]
        float* rawS  = sm + 128 * 130;     // [128][129]
        const float* adjr = adj + (size_t)blockIdx.x * 128;
        #pragma unroll
        for (int m = 0; m < MW; m++)
            #pragma unroll
            for (int j = 0; j < NJ; j++) {
                int row  = row0 + m * 16 + r;
                int lcol = wxn0 + j * 8 + 2 * c;
                int gcol = n0 + lcol;
                float b0 = bias[gcol], b1 = bias[gcol + 1];
                float a0 = adjr[lcol], a1 = adjr[lcol + 1];
                *(float2*)&logit[row * 130 + lcol] =
                    make_float2(a0 + 0.1f * (acc[m][j][0] + b0),
                                a1 + 0.1f * (acc[m][j][1] + b1));
                *(float2*)&logit[(row + 8) * 130 + lcol] =
                    make_float2(a0 + 0.1f * (acc[m][j][2] + b0),
                                a1 + 0.1f * (acc[m][j][3] + b1));
            }
        #pragma unroll
        for (int u = 0; u < 16; u++) {
            int i4 = tid + u * 256;                         // 0..4095
            float4 v = ((const float4*)raw)[i4];
            int b = i4 >> 5, j4 = (i4 & 31) * 4;
            float* d = &rawS[b * 129 + j4];
            d[0] = v.x; d[1] = v.y; d[2] = v.z; d[3] = v.w;
        }
        __syncthreads();
        if (tid < 128) {
            const float* L = &logit[tid * 130];
            const float* R = &rawS[tid * 129];
            float mx = -1e30f;
            #pragma unroll 4
            for (int j = 0; j < 128; j++) mx = fmaxf(mx, L[j]);
            float sum = 0.f, dot = 0.f;
            #pragma unroll 4
            for (int j = 0; j < 128; j++) {
                float e = __expf(L[j] - mx);
                sum += e;
                dot += e * R[j];
            }
            float w = dot / sum;
            out[(size_t)tid * N_ + blockIdx.x] = 1.f / (1.f + __expf(-w));
        }
    }
}

// ---------------- fused ctx-reduce + raw split-K partials ----------------
// grid 128 (K chunks of 16), block 256.
__global__ void k_rawctx(const float* __restrict__ ctxp, const float* __restrict__ bc,
                         const float* __restrict__ rs, float* __restrict__ part,
                         __nv_bfloat16* __restrict__ ctxbf) {
    __shared__ float cs [128][20];
    __shared__ float rss[128][20];
    const int tid = threadIdx.x;
    const int k0  = blockIdx.x * 16;
    const float* p0 = ctxp;
    const float* p1 = ctxp + (size_t)B_ * D_;
    #pragma unroll
    for (int u = 0; u < 2; u++) {
        int i  = tid + u * 256;
        int rr = i >> 2, cc = (i & 3) * 4;
        float4 a  = *(const float4*)&p0[(size_t)rr * D_ + k0 + cc];
        float4 b  = *(const float4*)&p1[(size_t)rr * D_ + k0 + cc];
        float4 bv = *(const float4*)&bc[k0 + cc];
        float4 s;
        s.x = a.x + b.x + bv.x; s.y = a.y + b.y + bv.y;
        s.z = a.z + b.z + bv.z; s.w = a.w + b.w + bv.w;
        *(float4*)&cs[rr][cc] = s;
        *(uint2*)&ctxbf[(size_t)rr * D_ + k0 + cc] =
            make_uint2(f2bf2(s.x, s.y), f2bf2(s.z, s.w));
        *(float4*)&rss[rr][cc] = *(const float4*)&rs[(size_t)rr * D_ + k0 + cc];
    }
    __syncthreads();
    const int bb = tid >> 4;
    const int jj = tid & 15;
    float a[8][8];
    #pragma unroll
    for (int u = 0; u < 8; u++)
        #pragma unroll
        for (int v = 0; v < 8; v++) a[u][v] = 0.f;
    #pragma unroll
    for (int k = 0; k < 16; k++) {
        float cv[8], rv[8];
        #pragma unroll
        for (int u = 0; u < 8; u++) { cv[u] = cs[bb + 16*u][k]; rv[u] = rss[jj + 16*u][k]; }
        #pragma unroll
        for (int u = 0; u < 8; u++)
            #pragma unroll
            for (int v = 0; v < 8; v++) a[u][v] += cv[u] * rv[v];
    }
    float* po = part + (size_t)blockIdx.x * NN_;
    #pragma unroll
    for (int u = 0; u < 8; u++)
        #pragma unroll
        for (int v = 0; v < 8; v++)
            po[(bb + 16*u) * N_ + (jj + 16*v)] = a[u][v];
}

// ---------------- raw reduce: grid 128, float4, 8-way ks split ----------------
__global__ void k_rawred(const float4* __restrict__ part4, float4* __restrict__ raw4) {
    __shared__ float4 red[8][32];
    const int g  = threadIdx.x >> 5;                  // ks group 0..7 (16 ks each)
    const int o4 = threadIdx.x & 31;                  // output float4 within block
    const int oi = (blockIdx.x << 5) + o4;            // 0..4095
    float4 s = make_float4(0.f, 0.f, 0.f, 0.f);
    #pragma unroll
    for (int ks = g * 16; ks < g * 16 + 16; ks++) {
        float4 v = part4[(size_t)ks * (NN_ / 4) + oi];
        s.x += v.x; s.y += v.y; s.z += v.z; s.w += v.w;
    }
    red[g][o4] = s;
    __syncthreads();
    if (threadIdx.x < 32) {
        float4 t = make_float4(0.f, 0.f, 0.f, 0.f);
        #pragma unroll
        for (int q = 0; q < 8; q += 2) {
            float4 a = red[q][threadIdx.x], b = red[q + 1][threadIdx.x];
            t.x += a.x + b.x; t.y += a.y + b.y;
            t.z += a.z + b.z; t.w += a.w + b.w;
        }
        raw4[(blockIdx.x << 5) + threadIdx.x] = t;
    }
}

// ---------------- launch ----------------
extern "C" void kernel_launch(void* const* d_in, const int* in_sizes, int n_in,
                              void* d_out, int out_size) {
    const float* x   = (const float*)d_in[0];
    const float* rs  = (const float*)d_in[1];
    const float* Wc  = (const float*)d_in[2];
    const float* bc  = (const float*)d_in[3];
    const float* Ww  = (const float*)d_in[4];
    const float* bw  = (const float*)d_in[5];
    const float* adj = (const float*)d_in[6];
    float* out = (float*)d_out;

    __nv_bfloat16 *p_meanbf, *p_ctxbf;
    float *p_ctxp, *p_part, *p_raw;
    cudaGetSymbolAddress((void**)&p_meanbf, g_meanbf);
    cudaGetSymbolAddress((void**)&p_ctxbf, g_ctxbf);
    cudaGetSymbolAddress((void**)&p_ctxp,  g_ctxp);
    cudaGetSymbolAddress((void**)&p_part,  g_part);
    cudaGetSymbolAddress((void**)&p_raw,   g_raw);

    // 1. mean over S (HBM-bound, 512 MB) -> bf16
    k_mean<<<B_ * 8, 64>>>((const float4*)x, (uint2*)p_meanbf);

    // 2. context partials: split-K x2, 128 blocks, warps 4x2
    {
        size_t sh = 64 + (size_t)STG * (ATB + 32 * BRS);
        cudaFuncSetAttribute((const void*)k_gemm<32, D_, 0, 4, 2>,
                             cudaFuncAttributeMaxDynamicSharedMemorySize, (int)sh);
        k_gemm<32, D_, 0, 4, 2><<<128, 256, sh>>>(p_meanbf, Wc, nullptr, p_ctxp,
                                                  nullptr, nullptr);
    }

    // 3. fused: ctx = p0+p1+bc (-> bf16) + raw split-K partials; then reduce
    k_rawctx<<<128, 256>>>(p_ctxp, bc, rs, p_part, p_ctxbf);
    k_rawred<<<128, 256>>>((const float4*)p_part, (float4*)p_raw);

    // 4+5. warp GEMM + fused softmax/einsum/sigmoid, warps 2x4
    {
        size_t stages = 64 + (size_t)STG * (ATB + 128 * BRS);          // 221,248 B
        size_t epi    = (size_t)(128 * 130 + 128 * 129) * 4;           // 132,608 B
        size_t sh     = stages > epi ? stages : epi;
        cudaFuncSetAttribute((const void*)k_gemm<128, NN_, 3, 2, 4>,
                             cudaFuncAttributeMaxDynamicSharedMemorySize, (int)sh);
        k_gemm<128, NN_, 3, 2, 4><<<128, 256, sh>>>(p_ctxbf, Ww, bw, out, adj, p_raw);
    }
}

// round 16
// speedup vs baseline: 1.1420x; 1.1420x over previous
#include <cuda_runtime.h>
#include <cuda_bf16.h>
#include <cstdint>

#define B_    128
#define S_    512
#define D_    2048
#define N_    128
#define NN_   16384
#define KTILE 64
#define ABW   144    /* A (bf16) smem row stride bytes: 128 data + 16 pad */
#define BPAD  72     /* B (fp32) smem row stride floats: 64 data + 8 pad */
#define STG   4
#define ATB   (128 * ABW)

// ---------------- scratch (device globals; no allocation) ----------------
__device__ __align__(16) __nv_bfloat16 g_meanbf[B_ * D_];  // 0.5 MB
__device__ __align__(16) __nv_bfloat16 g_ctxbf[B_ * D_];   // 0.5 MB (bf16 ctx, gemm2 A)
__device__ __align__(16) float g_ctxp[2 * B_ * D_];        // 2 MB gemm1 split-K partials
__device__ __align__(16) float g_part[128 * NN_];          // 8 MB raw split-K partials
__device__ __align__(16) float g_raw [NN_];                // 64 KB
__device__ __align__(16) float g_sink[128 * 256];          // 128 KB prefetch checksums

// ---------------- helpers ----------------
__device__ __forceinline__ void cp_async16(void* smem, const void* gmem) {
    uint32_t s = (uint32_t)__cvta_generic_to_shared(smem);
    asm volatile("cp.async.cg.shared.global [%0], [%1], 16;\n" :: "r"(s), "l"(gmem));
}
__device__ __forceinline__ uint32_t f2bf2(float lo, float hi) {
    uint32_t r;
    asm("cvt.rn.bf16x2.f32 %0, %1, %2;" : "=r"(r) : "f"(hi), "f"(lo));  // hi -> upper 16
    return r;
}
__device__ __forceinline__ void mma_bf16(float* c, const uint32_t* a, const uint32_t* b) {
    asm volatile(
        "mma.sync.aligned.m16n8k16.row.col.f32.bf16.bf16.f32 "
        "{%0,%1,%2,%3}, {%4,%5,%6,%7}, {%8,%9}, {%0,%1,%2,%3};"
        : "+f"(c[0]), "+f"(c[1]), "+f"(c[2]), "+f"(c[3])
        : "r"(a[0]), "r"(a[1]), "r"(a[2]), "r"(a[3]), "r"(b[0]), "r"(b[1]));
}

// ---------------- kernel 1: mean over sequence -> bf16 ----------------
__global__ void k_mean(const float4* __restrict__ x4, uint2* __restrict__ mbf) {
    int b  = blockIdx.x >> 3;
    int d4 = ((blockIdx.x & 7) << 6) + threadIdx.x;     // 0..511
    const float4* p = x4 + (size_t)b * (S_ * D_ / 4) + d4;
    float4 acc[8];
    #pragma unroll
    for (int u = 0; u < 8; u++) acc[u] = make_float4(0.f, 0.f, 0.f, 0.f);
    for (int s = 0; s < S_; s += 8) {
        #pragma unroll
        for (int u = 0; u < 8; u++) {
            float4 v = __ldcs(&p[(size_t)(s + u) * (D_ / 4)]);
            acc[u].x += v.x; acc[u].y += v.y; acc[u].z += v.z; acc[u].w += v.w;
        }
    }
    #pragma unroll
    for (int u = 0; u < 4; u++) {
        acc[u].x += acc[u+4].x; acc[u].y += acc[u+4].y;
        acc[u].z += acc[u+4].z; acc[u].w += acc[u+4].w;
    }
    acc[0].x += acc[2].x; acc[0].y += acc[2].y; acc[0].z += acc[2].z; acc[0].w += acc[2].w;
    acc[1].x += acc[3].x; acc[1].y += acc[3].y; acc[1].z += acc[3].z; acc[1].w += acc[3].w;
    const float inv = 1.f / (float)S_;
    float mx = (acc[0].x + acc[1].x) * inv;
    float my = (acc[0].y + acc[1].y) * inv;
    float mz = (acc[0].z + acc[1].z) * inv;
    float mw = (acc[0].w + acc[1].w) * inv;
    mbf[b * (D_ / 4) + d4] = make_uint2(f2bf2(mx, my), f2bf2(mz, mw));
}

// ---------------- cp.async 4-stage GEMM: A bf16-smem, B fp32-smem ----------------
// out[128, NFULL] = A[128,2048] @ Bm[NFULL,2048]^T; NT cols per block.
// First 256 threads = 8 gemm warps laid out WY(M) x WX(N). Single sync per ktile.
// MODE 0: split-K x2 partials (launched with 512 threads: threads 256..511 are
//         prefetch warps streaming 512KB of pf into L2, pacing with nkt syncs).
// MODE 3: full-K + fused softmax/einsum/sigmoid epilogue (NT = 128, 256 threads).
template<int NT, int NFULL, int MODE, int WY, int WX>
__global__ void __launch_bounds__(512, 1)
k_gemm(const __nv_bfloat16* __restrict__ Abf, const float* __restrict__ Bm,
       const float* __restrict__ bias, float* __restrict__ out,
       const float* __restrict__ adj, const float* __restrict__ raw,
       const float4* __restrict__ pf, float* __restrict__ sink) {
    constexpr int BTB = NT * BPAD * 4;   // B tile bytes per stage
    constexpr int MW  = 128 / WY / 16;   // m16 tiles per warp
    constexpr int NJ  = NT / WX / 8;     // n8 tiles per warp
    constexpr int NAC = 4;               // A cp.async per thread (128*8/256)
    constexpr int NBC = NT * 16 / 256;   // B cp.async per thread

    extern __shared__ __align__(16) char smch[];
    float* sm = (float*)smch;
    char* Ab = smch;                      // [STG][128][ABW]
    char* Bb = smch + STG * ATB;          // [STG][NT][BPAD*4]

    const int tid  = threadIdx.x;

    int n0, k0g, nkt;
    float* op = out;
    if (MODE == 0) {
        const int nblk = NFULL / NT;
        int split = blockIdx.x / nblk;
        n0  = (blockIdx.x % nblk) * NT;
        k0g = split * (D_ / 2);
        nkt = (D_ / 2) / KTILE;           // 16
        op  = out + (size_t)split * 128 * NFULL;
    } else {
        n0 = blockIdx.x * NT; k0g = 0; nkt = D_ / KTILE;   // 32
    }

    // ---- prefetch warps (MODE 0, tid >= 256): stream 512KB of pf into L2 ----
    if (MODE == 0 && tid >= 256) {
        const int pt = tid - 256;                         // 0..255
        const float4* base = pf + (size_t)blockIdx.x * 32768;
        float acc = 0.f;
        for (int kt = 0; kt < nkt; kt++) {
            #pragma unroll
            for (int u = 0; u < 8; u++) {
                float4 v = __ldcg(&base[kt * 2048 + pt + u * 256]);
                acc += v.x + v.y + v.z + v.w;
            }
            __syncthreads();                              // mirrors gemm loop syncs
        }
        sink[blockIdx.x * 256 + pt] = acc;
        return;
    }

    const int warp = tid >> 5, lane = tid & 31;
    const int wy   = warp / WX, wx = warp % WX;
    const int row0 = wy * (128 / WY);
    const int wxn0 = wx * (NT / WX);
    const int r    = lane >> 2, c = lane & 3;

    float acc[MW][NJ][4];
    #pragma unroll
    for (int m = 0; m < MW; m++)
        #pragma unroll
        for (int j = 0; j < NJ; j++)
            acc[m][j][0] = acc[m][j][1] = acc[m][j][2] = acc[m][j][3] = 0.f;

    auto issue = [&](int kt) {
        const int st = kt % STG;
        const int k0 = k0g + kt * KTILE;
        #pragma unroll
        for (int u = 0; u < NAC; u++) {               // A: 128 rows x 64 bf16 (8 x 16B)
            int i = tid + u * 256, rr = i >> 3, c8 = i & 7;
            cp_async16(Ab + st * ATB + rr * ABW + c8 * 16,
                       &Abf[(size_t)rr * D_ + k0 + c8 * 8]);
        }
        #pragma unroll
        for (int u = 0; u < NBC; u++) {               // B: NT rows x 64 fp32 (16 x 16B)
            int i = tid + u * 256, rr = i >> 4, c16 = i & 15;
            cp_async16(Bb + st * BTB + rr * (BPAD * 4) + c16 * 16,
                       &Bm[(size_t)(n0 + rr) * D_ + k0 + c16 * 4]);
        }
    };

    #pragma unroll
    for (int s = 0; s < STG - 1; s++) {
        issue(s);
        asm volatile("cp.async.commit_group;\n");
    }

    for (int kt = 0; kt < nkt; kt++) {
        const int st = kt % STG;
        asm volatile("cp.async.wait_group %0;\n" :: "n"(STG - 2));
        __syncthreads();
        // issue(kt+3) overwrites stage (kt-1)%4; consumed at iter kt-1 before this sync.
        if (kt + STG - 1 < nkt) issue(kt + STG - 1);
        asm volatile("cp.async.commit_group;\n");

        const char*  Ast = Ab + st * ATB;
        const float* Bst = (const float*)(Bb + st * BTB);
        #pragma unroll
        for (int h = 0; h < 4; h++) {
            const int cb = h * 32 + 4 * c;            // A byte offset of k = 16h + 2c
            const int kb = h * 16 + 2 * c;            // B float offset
            uint32_t a[MW][4];
            #pragma unroll
            for (int m = 0; m < MW; m++) {
                const char* ap = Ast + (row0 + m * 16 + r) * ABW;
                a[m][0] = *(const uint32_t*)(ap + cb);
                a[m][1] = *(const uint32_t*)(ap + 8 * ABW + cb);
                a[m][2] = *(const uint32_t*)(ap + cb + 16);
                a[m][3] = *(const uint32_t*)(ap + 8 * ABW + cb + 16);
            }
            #pragma unroll
            for (int j = 0; j < NJ; j++) {
                const float* bp = Bst + (wxn0 + j * 8 + r) * BPAD + kb;
                float2 v;
                uint32_t b[2];
                v = *(const float2*)(bp);       b[0] = f2bf2(v.x, v.y);
                v = *(const float2*)(bp + 8);   b[1] = f2bf2(v.x, v.y);
                #pragma unroll
                for (int m = 0; m < MW; m++) mma_bf16(acc[m][j], a[m], b);
            }
        }
    }

    if (MODE == 0) {
        #pragma unroll
        for (int m = 0; m < MW; m++)
            #pragma unroll
            for (int j = 0; j < NJ; j++) {
                int row = row0 + m * 16 + r;
                int col = n0 + wxn0 + j * 8 + 2 * c;
                *(float2*)&op[(size_t)row * NFULL + col] =
                    make_float2(acc[m][j][0], acc[m][j][1]);
                *(float2*)&op[(size_t)(row + 8) * NFULL + col] =
                    make_float2(acc[m][j][2], acc[m][j][3]);
            }
    } else {
        // fused: logits = adj[i,:] + 0.1*(acc + bw); softmax over j; dot raw; sigmoid
        asm volatile("cp.async.wait_group 0;\n");
        __syncthreads();
        float* logit = sm;                 // [128][130]
        float* rawS  = sm + 128 * 130;     // [128][129]
        const float* adjr = adj + (size_t)blockIdx.x * 128;
        #pragma unroll
        for (int m = 0; m < MW; m++)
            #pragma unroll
            for (int j = 0; j < NJ; j++) {
                int row  = row0 + m * 16 + r;
                int lcol = wxn0 + j * 8 + 2 * c;
                int gcol = n0 + lcol;
                float b0 = bias[gcol], b1 = bias[gcol + 1];
                float a0 = adjr[lcol], a1 = adjr[lcol + 1];
                *(float2*)&logit[row * 130 + lcol] =
                    make_float2(a0 + 0.1f * (acc[m][j][0] + b0),
                                a1 + 0.1f * (acc[m][j][1] + b1));
                *(float2*)&logit[(row + 8) * 130 + lcol] =
                    make_float2(a0 + 0.1f * (acc[m][j][2] + b0),
                                a1 + 0.1f * (acc[m][j][3] + b1));
            }
        #pragma unroll
        for (int u = 0; u < 16; u++) {
            int i4 = tid + u * 256;                         // 0..4095
            float4 v = ((const float4*)raw)[i4];
            int b = i4 >> 5, j4 = (i4 & 31) * 4;
            float* d = &rawS[b * 129 + j4];
            d[0] = v.x; d[1] = v.y; d[2] = v.z; d[3] = v.w;
        }
        __syncthreads();
        if (tid < 128) {
            const float* L = &logit[tid * 130];
            const float* R = &rawS[tid * 129];
            float mx = -1e30f;
            #pragma unroll 4
            for (int j = 0; j < 128; j++) mx = fmaxf(mx, L[j]);
            float sum = 0.f, dot = 0.f;
            #pragma unroll 4
            for (int j = 0; j < 128; j++) {
                float e = __expf(L[j] - mx);
                sum += e;
                dot += e * R[j];
            }
            float w = dot / sum;
            out[(size_t)tid * N_ + blockIdx.x] = 1.f / (1.f + __expf(-w));
        }
    }
}

// ---------------- fused ctx-reduce + raw split-K partials ----------------
// grid 128 (K chunks of 16), block 256.
__global__ void k_rawctx(const float* __restrict__ ctxp, const float* __restrict__ bc,
                         const float* __restrict__ rs, float* __restrict__ part,
                         __nv_bfloat16* __restrict__ ctxbf) {
    __shared__ float cs [128][20];
    __shared__ float rss[128][20];
    const int tid = threadIdx.x;
    const int k0  = blockIdx.x * 16;
    const float* p0 = ctxp;
    const float* p1 = ctxp + (size_t)B_ * D_;
    #pragma unroll
    for (int u = 0; u < 2; u++) {
        int i  = tid + u * 256;
        int rr = i >> 2, cc = (i & 3) * 4;
        float4 a  = *(const float4*)&p0[(size_t)rr * D_ + k0 + cc];
        float4 b  = *(const float4*)&p1[(size_t)rr * D_ + k0 + cc];
        float4 bv = *(const float4*)&bc[k0 + cc];
        float4 s;
        s.x = a.x + b.x + bv.x; s.y = a.y + b.y + bv.y;
        s.z = a.z + b.z + bv.z; s.w = a.w + b.w + bv.w;
        *(float4*)&cs[rr][cc] = s;
        *(uint2*)&ctxbf[(size_t)rr * D_ + k0 + cc] =
            make_uint2(f2bf2(s.x, s.y), f2bf2(s.z, s.w));
        *(float4*)&rss[rr][cc] = *(const float4*)&rs[(size_t)rr * D_ + k0 + cc];
    }
    __syncthreads();
    const int bb = tid >> 4;
    const int jj = tid & 15;
    float a[8][8];
    #pragma unroll
    for (int u = 0; u < 8; u++)
        #pragma unroll
        for (int v = 0; v < 8; v++) a[u][v] = 0.f;
    #pragma unroll
    for (int k = 0; k < 16; k++) {
        float cv[8], rv[8];
        #pragma unroll
        for (int u = 0; u < 8; u++) { cv[u] = cs[bb + 16*u][k]; rv[u] = rss[jj + 16*u][k]; }
        #pragma unroll
        for (int u = 0; u < 8; u++)
            #pragma unroll
            for (int v = 0; v < 8; v++) a[u][v] += cv[u] * rv[v];
    }
    float* po = part + (size_t)blockIdx.x * NN_;
    #pragma unroll
    for (int u = 0; u < 8; u++)
        #pragma unroll
        for (int v = 0; v < 8; v++)
            po[(bb + 16*u) * N_ + (jj + 16*v)] = a[u][v];
}

// ---------------- raw reduce: grid 128, float4, 8-way ks split ----------------
__global__ void k_rawred(const float4* __restrict__ part4, float4* __restrict__ raw4) {
    __shared__ float4 red[8][32];
    const int g  = threadIdx.x >> 5;                  // ks group 0..7 (16 ks each)
    const int o4 = threadIdx.x & 31;                  // output float4 within block
    const int oi = (blockIdx.x << 5) + o4;            // 0..4095
    float4 s = make_float4(0.f, 0.f, 0.f, 0.f);
    #pragma unroll
    for (int ks = g * 16; ks < g * 16 + 16; ks++) {
        float4 v = part4[(size_t)ks * (NN_ / 4) + oi];
        s.x += v.x; s.y += v.y; s.z += v.z; s.w += v.w;
    }
    red[g][o4] = s;
    __syncthreads();
    if (threadIdx.x < 32) {
        float4 t = make_float4(0.f, 0.f, 0.f, 0.f);
        #pragma unroll
        for (int q = 0; q < 8; q += 2) {
            float4 a = red[q][threadIdx.x], b = red[q + 1][threadIdx.x];
            t.x += a.x + b.x; t.y += a.y + b.y;
            t.z += a.z + b.z; t.w += a.w + b.w;
        }
        raw4[(blockIdx.x << 5) + threadIdx.x] = t;
    }
}

// ---------------- launch ----------------
extern "C" void kernel_launch(void* const* d_in, const int* in_sizes, int n_in,
                              void* d_out, int out_size) {
    const float* x   = (const float*)d_in[0];
    const float* rs  = (const float*)d_in[1];
    const float* Wc  = (const float*)d_in[2];
    const float* bc  = (const float*)d_in[3];
    const float* Ww  = (const float*)d_in[4];
    const float* bw  = (const float*)d_in[5];
    const float* adj = (const float*)d_in[6];
    float* out = (float*)d_out;

    __nv_bfloat16 *p_meanbf, *p_ctxbf;
    float *p_ctxp, *p_part, *p_raw, *p_sink;
    cudaGetSymbolAddress((void**)&p_meanbf, g_meanbf);
    cudaGetSymbolAddress((void**)&p_ctxbf, g_ctxbf);
    cudaGetSymbolAddress((void**)&p_ctxp,  g_ctxp);
    cudaGetSymbolAddress((void**)&p_part,  g_part);
    cudaGetSymbolAddress((void**)&p_raw,   g_raw);
    cudaGetSymbolAddress((void**)&p_sink,  g_sink);

    // 1. mean over S (HBM-bound, 512 MB) -> bf16
    k_mean<<<B_ * 8, 64>>>((const float4*)x, (uint2*)p_meanbf);

    // 2. context partials (split-K x2, 128 blocks, warps 4x2) + Ww[0:64MB] L2 prefetch
    {
        size_t sh = (size_t)STG * (ATB + 32 * BPAD * 4);
        cudaFuncSetAttribute((const void*)k_gemm<32, D_, 0, 4, 2>,
                             cudaFuncAttributeMaxDynamicSharedMemorySize, (int)sh);
        k_gemm<32, D_, 0, 4, 2><<<128, 512, sh>>>(p_meanbf, Wc, nullptr, p_ctxp,
                                                  nullptr, nullptr,
                                                  (const float4*)Ww, p_sink);
    }

    // 3. fused: ctx = p0+p1+bc (-> bf16) + raw split-K partials; then reduce
    k_rawctx<<<128, 256>>>(p_ctxp, bc, rs, p_part, p_ctxbf);
    k_rawred<<<128, 256>>>((const float4*)p_part, (float4*)p_raw);

    // 4+5. warp GEMM + fused softmax/einsum/sigmoid, warps 2x4
    {
        size_t stages = (size_t)STG * (ATB + 128 * BPAD * 4);          // 221,184 B
        size_t epi    = (size_t)(128 * 130 + 128 * 129) * 4;           // 132,608 B
        size_t sh     = stages > epi ? stages : epi;
        cudaFuncSetAttribute((const void*)k_gemm<128, NN_, 3, 2, 4>,
                             cudaFuncAttributeMaxDynamicSharedMemorySize, (int)sh);
        k_gemm<128, NN_, 3, 2, 4><<<128, 256, sh>>>(p_ctxbf, Ww, bw, out, adj, p_raw,
                                                    nullptr, nullptr);
    }
}

// round 17
// speedup vs baseline: 1.1557x; 1.0120x over previous
#include <cuda_runtime.h>
#include <cuda_bf16.h>
#include <cstdint>

#define B_    128
#define S_    512
#define D_    2048
#define N_    128
#define NN_   16384
#define KTILE 64
#define ABW   144    /* A (bf16) smem row stride bytes: 128 data + 16 pad */
#define BPAD  72     /* B (fp32) smem row stride floats: 64 data + 8 pad */
#define STG   4
#define ATB   (128 * ABW)
#define KS1   4      /* gemm1 k-splits */

// ---------------- scratch (device globals; no allocation) ----------------
__device__ __align__(16) __nv_bfloat16 g_meanbf[B_ * D_];  // 0.5 MB
__device__ __align__(16) __nv_bfloat16 g_ctxbf[B_ * D_];   // 0.5 MB (bf16 ctx, gemm2 A)
__device__ __align__(16) float g_ctxp[KS1 * B_ * D_];      // 4 MB gemm1 split-K partials
__device__ __align__(16) float g_part[128 * NN_];          // 8 MB raw split-K partials
__device__ __align__(16) float g_raw [NN_];                // 64 KB

// ---------------- helpers ----------------
__device__ __forceinline__ void cp_async16(void* smem, const void* gmem) {
    uint32_t s = (uint32_t)__cvta_generic_to_shared(smem);
    asm volatile("cp.async.cg.shared.global [%0], [%1], 16;\n" :: "r"(s), "l"(gmem));
}
__device__ __forceinline__ uint32_t f2bf2(float lo, float hi) {
    uint32_t r;
    asm("cvt.rn.bf16x2.f32 %0, %1, %2;" : "=r"(r) : "f"(hi), "f"(lo));  // hi -> upper 16
    return r;
}
__device__ __forceinline__ void mma_bf16(float* c, const uint32_t* a, const uint32_t* b) {
    asm volatile(
        "mma.sync.aligned.m16n8k16.row.col.f32.bf16.bf16.f32 "
        "{%0,%1,%2,%3}, {%4,%5,%6,%7}, {%8,%9}, {%0,%1,%2,%3};"
        : "+f"(c[0]), "+f"(c[1]), "+f"(c[2]), "+f"(c[3])
        : "r"(a[0]), "r"(a[1]), "r"(a[2]), "r"(a[3]), "r"(b[0]), "r"(b[1]));
}

// ---------------- kernel 1: mean over sequence -> bf16 ----------------
__global__ void k_mean(const float4* __restrict__ x4, uint2* __restrict__ mbf) {
    int b  = blockIdx.x >> 3;
    int d4 = ((blockIdx.x & 7) << 6) + threadIdx.x;     // 0..511
    const float4* p = x4 + (size_t)b * (S_ * D_ / 4) + d4;
    float4 acc[8];
    #pragma unroll
    for (int u = 0; u < 8; u++) acc[u] = make_float4(0.f, 0.f, 0.f, 0.f);
    for (int s = 0; s < S_; s += 8) {
        #pragma unroll
        for (int u = 0; u < 8; u++) {
            float4 v = __ldcs(&p[(size_t)(s + u) * (D_ / 4)]);
            acc[u].x += v.x; acc[u].y += v.y; acc[u].z += v.z; acc[u].w += v.w;
        }
    }
    #pragma unroll
    for (int u = 0; u < 4; u++) {
        acc[u].x += acc[u+4].x; acc[u].y += acc[u+4].y;
        acc[u].z += acc[u+4].z; acc[u].w += acc[u+4].w;
    }
    acc[0].x += acc[2].x; acc[0].y += acc[2].y; acc[0].z += acc[2].z; acc[0].w += acc[2].w;
    acc[1].x += acc[3].x; acc[1].y += acc[3].y; acc[1].z += acc[3].z; acc[1].w += acc[3].w;
    const float inv = 1.f / (float)S_;
    float mx = (acc[0].x + acc[1].x) * inv;
    float my = (acc[0].y + acc[1].y) * inv;
    float mz = (acc[0].z + acc[1].z) * inv;
    float mw = (acc[0].w + acc[1].w) * inv;
    mbf[b * (D_ / 4) + d4] = make_uint2(f2bf2(mx, my), f2bf2(mz, mw));
}

// ---------------- cp.async 4-stage GEMM: A bf16-smem, B fp32-smem ----------------
// out[128, NFULL] = A[128,2048] @ Bm[NFULL,2048]^T; NT cols per block.
// 256 threads = 8 warps laid out WY(M) x WX(N). Single sync per ktile.
// MODE 0: split-K x KSPLIT partials. grid = KSPLIT * NFULL/NT. out[split][128][NFULL].
// MODE 3: full-K + fused softmax/einsum/sigmoid epilogue (NT = 128).
template<int NT, int NFULL, int MODE, int WY, int WX, int KSPLIT>
__global__ void __launch_bounds__(256, 1)
k_gemm(const __nv_bfloat16* __restrict__ Abf, const float* __restrict__ Bm,
       const float* __restrict__ bias, float* __restrict__ out,
       const float* __restrict__ adj, const float* __restrict__ raw) {
    constexpr int BTB = NT * BPAD * 4;   // B tile bytes per stage
    constexpr int MW  = 128 / WY / 16;   // m16 tiles per warp
    constexpr int NJ  = NT / WX / 8;     // n8 tiles per warp
    constexpr int NAC = 4;               // A cp.async per thread (128*8/256)
    constexpr int NBC = NT * 16 / 256;   // B cp.async per thread

    extern __shared__ __align__(16) char smch[];
    float* sm = (float*)smch;
    char* Ab = smch;                      // [STG][128][ABW]
    char* Bb = smch + STG * ATB;          // [STG][NT][BPAD*4]

    const int tid  = threadIdx.x;
    const int warp = tid >> 5, lane = tid & 31;
    const int wy   = warp / WX, wx = warp % WX;
    const int row0 = wy * (128 / WY);
    const int wxn0 = wx * (NT / WX);
    const int r    = lane >> 2, c = lane & 3;

    int n0, k0g, nkt;
    float* op = out;
    if (MODE == 0) {
        const int nblk = NFULL / NT;
        int split = blockIdx.x / nblk;
        n0  = (blockIdx.x % nblk) * NT;
        k0g = split * (D_ / KSPLIT);
        nkt = (D_ / KSPLIT) / KTILE;      // 8 for KSPLIT=4
        op  = out + (size_t)split * 128 * NFULL;
    } else {
        n0 = blockIdx.x * NT; k0g = 0; nkt = D_ / KTILE;   // 32
    }

    float acc[MW][NJ][4];
    #pragma unroll
    for (int m = 0; m < MW; m++)
        #pragma unroll
        for (int j = 0; j < NJ; j++)
            acc[m][j][0] = acc[m][j][1] = acc[m][j][2] = acc[m][j][3] = 0.f;

    auto issue = [&](int kt) {
        const int st = kt % STG;
        const int k0 = k0g + kt * KTILE;
        #pragma unroll
        for (int u = 0; u < NAC; u++) {               // A: 128 rows x 64 bf16 (8 x 16B)
            int i = tid + u * 256, rr = i >> 3, c8 = i & 7;
            cp_async16(Ab + st * ATB + rr * ABW + c8 * 16,
                       &Abf[(size_t)rr * D_ + k0 + c8 * 8]);
        }
        #pragma unroll
        for (int u = 0; u < NBC; u++) {               // B: NT rows x 64 fp32 (16 x 16B)
            int i = tid + u * 256, rr = i >> 4, c16 = i & 15;
            cp_async16(Bb + st * BTB + rr * (BPAD * 4) + c16 * 16,
                       &Bm[(size_t)(n0 + rr) * D_ + k0 + c16 * 4]);
        }
    };

    #pragma unroll
    for (int s = 0; s < STG - 1; s++) {
        issue(s);
        asm volatile("cp.async.commit_group;\n");
    }

    for (int kt = 0; kt < nkt; kt++) {
        const int st = kt % STG;
        asm volatile("cp.async.wait_group %0;\n" :: "n"(STG - 2));
        __syncthreads();
        // issue(kt+3) overwrites stage (kt-1)%4; consumed at iter kt-1 before this sync.
        if (kt + STG - 1 < nkt) issue(kt + STG - 1);
        asm volatile("cp.async.commit_group;\n");

        const char*  Ast = Ab + st * ATB;
        const float* Bst = (const float*)(Bb + st * BTB);
        #pragma unroll
        for (int h = 0; h < 4; h++) {
            const int cb = h * 32 + 4 * c;            // A byte offset of k = 16h + 2c
            const int kb = h * 16 + 2 * c;            // B float offset
            uint32_t a[MW][4];
            #pragma unroll
            for (int m = 0; m < MW; m++) {
                const char* ap = Ast + (row0 + m * 16 + r) * ABW;
                a[m][0] = *(const uint32_t*)(ap + cb);
                a[m][1] = *(const uint32_t*)(ap + 8 * ABW + cb);
                a[m][2] = *(const uint32_t*)(ap + cb + 16);
                a[m][3] = *(const uint32_t*)(ap + 8 * ABW + cb + 16);
            }
            #pragma unroll
            for (int j = 0; j < NJ; j++) {
                const float* bp = Bst + (wxn0 + j * 8 + r) * BPAD + kb;
                float2 v;
                uint32_t b[2];
                v = *(const float2*)(bp);       b[0] = f2bf2(v.x, v.y);
                v = *(const float2*)(bp + 8);   b[1] = f2bf2(v.x, v.y);
                #pragma unroll
                for (int m = 0; m < MW; m++) mma_bf16(acc[m][j], a[m], b);
            }
        }
    }

    if (MODE == 0) {
        #pragma unroll
        for (int m = 0; m < MW; m++)
            #pragma unroll
            for (int j = 0; j < NJ; j++) {
                int row = row0 + m * 16 + r;
                int col = n0 + wxn0 + j * 8 + 2 * c;
                *(float2*)&op[(size_t)row * NFULL + col] =
                    make_float2(acc[m][j][0], acc[m][j][1]);
                *(float2*)&op[(size_t)(row + 8) * NFULL + col] =
                    make_float2(acc[m][j][2], acc[m][j][3]);
            }
    } else {
        // fused: logits = adj[i,:] + 0.1*(acc + bw); softmax over j; dot raw; sigmoid
        asm volatile("cp.async.wait_group 0;\n");
        __syncthreads();
        float* logit = sm;                 // [128][130]
        float* rawS  = sm + 128 * 130;     // [128][129]
        const float* adjr = adj + (size_t)blockIdx.x * 128;
        #pragma unroll
        for (int m = 0; m < MW; m++)
            #pragma unroll
            for (int j = 0; j < NJ; j++) {
                int row  = row0 + m * 16 + r;
                int lcol = wxn0 + j * 8 + 2 * c;
                int gcol = n0 + lcol;
                float b0 = bias[gcol], b1 = bias[gcol + 1];
                float a0 = adjr[lcol], a1 = adjr[lcol + 1];
                *(float2*)&logit[row * 130 + lcol] =
                    make_float2(a0 + 0.1f * (acc[m][j][0] + b0),
                                a1 + 0.1f * (acc[m][j][1] + b1));
                *(float2*)&logit[(row + 8) * 130 + lcol] =
                    make_float2(a0 + 0.1f * (acc[m][j][2] + b0),
                                a1 + 0.1f * (acc[m][j][3] + b1));
            }
        #pragma unroll
        for (int u = 0; u < 16; u++) {
            int i4 = tid + u * 256;                         // 0..4095
            float4 v = ((const float4*)raw)[i4];
            int b = i4 >> 5, j4 = (i4 & 31) * 4;
            float* d = &rawS[b * 129 + j4];
            d[0] = v.x; d[1] = v.y; d[2] = v.z; d[3] = v.w;
        }
        __syncthreads();
        if (tid < 128) {
            const float* L = &logit[tid * 130];
            const float* R = &rawS[tid * 129];
            float mx = -1e30f;
            #pragma unroll 4
            for (int j = 0; j < 128; j++) mx = fmaxf(mx, L[j]);
            float sum = 0.f, dot = 0.f;
            #pragma unroll 4
            for (int j = 0; j < 128; j++) {
                float e = __expf(L[j] - mx);
                sum += e;
                dot += e * R[j];
            }
            float w = dot / sum;
            out[(size_t)tid * N_ + blockIdx.x] = 1.f / (1.f + __expf(-w));
        }
    }
}

// ---------------- fused ctx-reduce (4 splits) + raw split-K partials ----------------
// grid 128 (K chunks of 16), block 256.
__global__ void k_rawctx(const float* __restrict__ ctxp, const float* __restrict__ bc,
                         const float* __restrict__ rs, float* __restrict__ part,
                         __nv_bfloat16* __restrict__ ctxbf) {
    __shared__ float cs [128][20];
    __shared__ float rss[128][20];
    const int tid = threadIdx.x;
    const int k0  = blockIdx.x * 16;
    const float* p0 = ctxp;
    const float* p1 = ctxp + (size_t)B_ * D_;
    const float* p2 = ctxp + (size_t)2 * B_ * D_;
    const float* p3 = ctxp + (size_t)3 * B_ * D_;
    #pragma unroll
    for (int u = 0; u < 2; u++) {
        int i  = tid + u * 256;
        int rr = i >> 2, cc = (i & 3) * 4;
        size_t off = (size_t)rr * D_ + k0 + cc;
        float4 a  = *(const float4*)&p0[off];
        float4 b  = *(const float4*)&p1[off];
        float4 c2 = *(const float4*)&p2[off];
        float4 d  = *(const float4*)&p3[off];
        float4 bv = *(const float4*)&bc[k0 + cc];
        float4 s;
        s.x = (a.x + b.x) + (c2.x + d.x) + bv.x;
        s.y = (a.y + b.y) + (c2.y + d.y) + bv.y;
        s.z = (a.z + b.z) + (c2.z + d.z) + bv.z;
        s.w = (a.w + b.w) + (c2.w + d.w) + bv.w;
        *(float4*)&cs[rr][cc] = s;
        *(uint2*)&ctxbf[off] = make_uint2(f2bf2(s.x, s.y), f2bf2(s.z, s.w));
        *(float4*)&rss[rr][cc] = *(const float4*)&rs[off];
    }
    __syncthreads();
    const int bb = tid >> 4;
    const int jj = tid & 15;
    float a[8][8];
    #pragma unroll
    for (int u = 0; u < 8; u++)
        #pragma unroll
        for (int v = 0; v < 8; v++) a[u][v] = 0.f;
    #pragma unroll
    for (int k = 0; k < 16; k++) {
        float cv[8], rv[8];
        #pragma unroll
        for (int u = 0; u < 8; u++) { cv[u] = cs[bb + 16*u][k]; rv[u] = rss[jj + 16*u][k]; }
        #pragma unroll
        for (int u = 0; u < 8; u++)
            #pragma unroll
            for (int v = 0; v < 8; v++) a[u][v] += cv[u] * rv[v];
    }
    float* po = part + (size_t)blockIdx.x * NN_;
    #pragma unroll
    for (int u = 0; u < 8; u++)
        #pragma unroll
        for (int v = 0; v < 8; v++)
            po[(bb + 16*u) * N_ + (jj + 16*v)] = a[u][v];
}

// ---------------- raw reduce: grid 128, float4, 8-way ks split ----------------
__global__ void k_rawred(const float4* __restrict__ part4, float4* __restrict__ raw4) {
    __shared__ float4 red[8][32];
    const int g  = threadIdx.x >> 5;                  // ks group 0..7 (16 ks each)
    const int o4 = threadIdx.x & 31;                  // output float4 within block
    const int oi = (blockIdx.x << 5) + o4;            // 0..4095
    float4 s = make_float4(0.f, 0.f, 0.f, 0.f);
    #pragma unroll
    for (int ks = g * 16; ks < g * 16 + 16; ks++) {
        float4 v = part4[(size_t)ks * (NN_ / 4) + oi];
        s.x += v.x; s.y += v.y; s.z += v.z; s.w += v.w;
    }
    red[g][o4] = s;
    __syncthreads();
    if (threadIdx.x < 32) {
        float4 t = make_float4(0.f, 0.f, 0.f, 0.f);
        #pragma unroll
        for (int q = 0; q < 8; q += 2) {
            float4 a = red[q][threadIdx.x], b = red[q + 1][threadIdx.x];
            t.x += a.x + b.x; t.y += a.y + b.y;
            t.z += a.z + b.z; t.w += a.w + b.w;
        }
        raw4[(blockIdx.x << 5) + threadIdx.x] = t;
    }
}

// ---------------- launch ----------------
extern "C" void kernel_launch(void* const* d_in, const int* in_sizes, int n_in,
                              void* d_out, int out_size) {
    const float* x   = (const float*)d_in[0];
    const float* rs  = (const float*)d_in[1];
    const float* Wc  = (const float*)d_in[2];
    const float* bc  = (const float*)d_in[3];
    const float* Ww  = (const float*)d_in[4];
    const float* bw  = (const float*)d_in[5];
    const float* adj = (const float*)d_in[6];
    float* out = (float*)d_out;

    __nv_bfloat16 *p_meanbf, *p_ctxbf;
    float *p_ctxp, *p_part, *p_raw;
    cudaGetSymbolAddress((void**)&p_meanbf, g_meanbf);
    cudaGetSymbolAddress((void**)&p_ctxbf, g_ctxbf);
    cudaGetSymbolAddress((void**)&p_ctxp,  g_ctxp);
    cudaGetSymbolAddress((void**)&p_part,  g_part);
    cudaGetSymbolAddress((void**)&p_raw,   g_raw);

    // 1. mean over S (HBM-bound, 512 MB) -> bf16
    k_mean<<<B_ * 8, 64>>>((const float4*)x, (uint2*)p_meanbf);

    // 2. context partials: split-K x4, 256 blocks, warps 4x2
    {
        size_t sh = (size_t)STG * (ATB + 32 * BPAD * 4);
        cudaFuncSetAttribute((const void*)k_gemm<32, D_, 0, 4, 2, KS1>,
                             cudaFuncAttributeMaxDynamicSharedMemorySize, (int)sh);
        k_gemm<32, D_, 0, 4, 2, KS1><<<KS1 * (D_ / 32), 256, sh>>>(
            p_meanbf, Wc, nullptr, p_ctxp, nullptr, nullptr);
    }

    // 3. fused: ctx = p0+p1+p2+p3+bc (-> bf16) + raw split-K partials; then reduce
    k_rawctx<<<128, 256>>>(p_ctxp, bc, rs, p_part, p_ctxbf);
    k_rawred<<<128, 256>>>((const float4*)p_part, (float4*)p_raw);

    // 4+5. warp GEMM + fused softmax/einsum/sigmoid, warps 2x4
    {
        size_t stages = (size_t)STG * (ATB + 128 * BPAD * 4);          // 221,184 B
        size_t epi    = (size_t)(128 * 130 + 128 * 129) * 4;           // 132,608 B
        size_t sh     = stages > epi ? stages : epi;
        cudaFuncSetAttribute((const void*)k_gemm<128, NN_, 3, 2, 4, 1>,
                             cudaFuncAttributeMaxDynamicSharedMemorySize, (int)sh);
        k_gemm<128, NN_, 3, 2, 4, 1><<<128, 256, sh>>>(p_ctxbf, Ww, bw, out, adj, p_raw);
    }
}